// round 13
// baseline (speedup 1.0000x reference)
#include <cuda_runtime.h>
#include <cstdint>
#include <cstddef>

#define BN   16384          // batch
#define TT   10             // timesteps
#define II   184            // input features
#define HH   128            // hidden
#define G4   512            // 4*H (gate width)
#define BT   (BN * TT)      // 163840 rows
#define KP1  192            // padded K for layer-1 xproj

// ---------------- scratch (device globals; allocation-free) ----------------
__device__ float g_xp_f[(size_t)BT * G4];
__device__ float g_xp_b[(size_t)BT * G4];
__device__ float g_out1[(size_t)BT * 256];
__device__ float g_out2[(size_t)BT * 256];
__device__ float g_xr[(size_t)BT * KP1];     // tf32-rounded, padded x
__device__ float g_wr[4][512 * 256];         // rounded, padded w_ih (f,b,f2,b2)

// ---------------- helpers ----------------
__device__ __forceinline__ float sigm(float x) {
    return 1.0f / (1.0f + __expf(-x));
}
__device__ __forceinline__ float tf32r(float x) {
    uint32_t r;
    asm("cvt.rna.tf32.f32 %0, %1;" : "=r"(r) : "f"(x));
    return __uint_as_float(r);
}
__device__ __forceinline__ void mma8(float c[4], const uint32_t a[4],
                                     const uint32_t b[2]) {
    asm volatile(
        "mma.sync.aligned.m16n8k8.row.col.f32.tf32.tf32.f32 "
        "{%0,%1,%2,%3}, {%4,%5,%6,%7}, {%8,%9}, {%0,%1,%2,%3};"
        : "+f"(c[0]), "+f"(c[1]), "+f"(c[2]), "+f"(c[3])
        : "r"(a[0]), "r"(a[1]), "r"(a[2]), "r"(a[3]), "r"(b[0]), "r"(b[1]));
}
#define FU __float_as_uint

__device__ __forceinline__ uint32_t smem_u32(const void* p) {
    uint32_t a;
    asm("{ .reg .u64 t; cvta.to.shared.u64 t, %1; cvt.u32.u64 %0, t; }"
        : "=r"(a) : "l"(p));
    return a;
}
__device__ __forceinline__ void st_peer(uint32_t local_addr, uint32_t peer_rank,
                                        float v) {
    uint32_t pa;
    asm volatile("mapa.shared::cluster.u32 %0, %1, %2;"
                 : "=r"(pa) : "r"(local_addr), "r"(peer_rank));
    asm volatile("st.shared::cluster.f32 [%0], %1;" :: "r"(pa), "f"(v)
                 : "memory");
}

// ============================================================================
// Pre-round pass: dst[row][0..KP) = tf32_rna(src[row][0..K)), zero-padded.
// ============================================================================
__global__ void round_pad(const float* __restrict__ src, float* __restrict__ dst,
                          int K, int KPp, long long total4)
{
    const long long i4 = (long long)blockIdx.x * blockDim.x + threadIdx.x;
    if (i4 >= total4) return;
    const int kp4 = KPp >> 2;
    const long long row = i4 / kp4;
    const int c = (int)(i4 % kp4) * 4;
    float4 v = make_float4(0.f, 0.f, 0.f, 0.f);
    if (c < K) v = *(const float4*)(src + row * K + c);
    float4 o = make_float4(tf32r(v.x), tf32r(v.y), tf32r(v.z), tf32r(v.w));
    *(float4*)(dst + row * KPp + c) = o;
}

// ============================================================================
// xproj GEMM v4: cp.async + ldmatrix tf32 MMA (R11 core) with
//  - 4-stage pipeline, issue-BEFORE-compute (3 chunks in flight)
//  - fwd/bwd fused via blockIdx.z (halves launches, A-tile L2 reuse x8)
// ============================================================================
#define XST      20480                 // stage bytes: A 128*80 + B 128*80
#define XP_SMEM  (4 * XST)             // 81920

__global__ __launch_bounds__(128, 2)
void xproj_mma(const float* __restrict__ A,
               const float* __restrict__ Wf, const float* __restrict__ Wb,
               const float* __restrict__ bihf, const float* __restrict__ bhhf,
               const float* __restrict__ bihb, const float* __restrict__ bhhb,
               float* __restrict__ Cf, float* __restrict__ Cb, int KPp)
{
    extern __shared__ char sx[];
    const uint32_t smb = smem_u32(sx);
    const int tid = threadIdx.x, l = tid & 31, w = tid >> 5;
    const int gid = l >> 2, tig = l & 3;
    const int nt = blockIdx.x, mt = blockIdx.y, z = blockIdx.z;
    const float* W   = z ? Wb   : Wf;
    const float* bih = z ? bihb : bihf;
    const float* bhh = z ? bhhb : bhhf;
    float*       C   = z ? Cb   : Cf;
    const int warpm = w >> 1, warpn = w & 1;
    const int nblk = KPp >> 4;

    const float* Ag = A + (size_t)mt * 128 * KPp;
    const float* Wg = W + (size_t)nt * 128 * KPp;

    const int ckg = tid & 3, crw = tid >> 2;

    auto issue = [&](int c) {
        const uint32_t sA = smb + (c & 3) * XST;
        const uint32_t sB = sA + 10240;
        const float* ga = Ag + c * 16 + ckg * 4;
        const float* gb = Wg + c * 16 + ckg * 4;
#pragma unroll
        for (int i = 0; i < 4; i++) {
            const int r = crw + i * 32;
            asm volatile("cp.async.cg.shared.global [%0], [%1], 16;"
                         :: "r"(sA + r * 80 + ckg * 16),
                            "l"(ga + (size_t)r * KPp) : "memory");
            asm volatile("cp.async.cg.shared.global [%0], [%1], 16;"
                         :: "r"(sB + r * 80 + ckg * 16),
                            "l"(gb + (size_t)r * KPp) : "memory");
        }
    };

    const int lj = l >> 3, li = l & 7;
    const uint32_t offA = (uint32_t)((warpm * 64 + (lj & 1) * 8 + li) * 80
                                     + (lj >> 1) * 16);
    const uint32_t offB = (uint32_t)(10240 + (warpn * 64 + (lj >> 1) * 8 + li) * 80
                                     + (lj & 1) * 16);

    float acc[4][8][4];
#pragma unroll
    for (int m2 = 0; m2 < 4; m2++)
#pragma unroll
        for (int nn = 0; nn < 8; nn++)
#pragma unroll
            for (int r = 0; r < 4; r++) acc[m2][nn][r] = 0.0f;

    issue(0); asm volatile("cp.async.commit_group;" ::: "memory");
    issue(1); asm volatile("cp.async.commit_group;" ::: "memory");
    issue(2); asm volatile("cp.async.commit_group;" ::: "memory");

    for (int c = 0; c < nblk; c++) {
        asm volatile("cp.async.wait_group 3;" ::: "memory");  // chunk c complete
        __syncthreads();
        // issue chunk c+3 now so its copy overlaps compute of chunk c
        if (c + 3 < nblk) issue(c + 3);
        asm volatile("cp.async.commit_group;" ::: "memory");  // empty ok
        const uint32_t stg = smb + (c & 3) * XST;
#pragma unroll
        for (int kk = 0; kk < 2; kk++) {
            uint32_t a[4][4], b[4][4];
#pragma unroll
            for (int m2 = 0; m2 < 4; m2++)
                asm volatile(
                    "ldmatrix.sync.aligned.m8n8.x4.shared.b16 {%0,%1,%2,%3}, [%4];"
                    : "=r"(a[m2][0]), "=r"(a[m2][1]),
                      "=r"(a[m2][2]), "=r"(a[m2][3])
                    : "r"(stg + offA + m2 * 1280 + kk * 32));
#pragma unroll
            for (int n2 = 0; n2 < 4; n2++)
                asm volatile(
                    "ldmatrix.sync.aligned.m8n8.x4.shared.b16 {%0,%1,%2,%3}, [%4];"
                    : "=r"(b[n2][0]), "=r"(b[n2][1]),
                      "=r"(b[n2][2]), "=r"(b[n2][3])
                    : "r"(stg + offB + n2 * 1280 + kk * 32));
#pragma unroll
            for (int m2 = 0; m2 < 4; m2++)
#pragma unroll
                for (int n2 = 0; n2 < 4; n2++) {
                    mma8(acc[m2][n2 * 2],     a[m2], &b[n2][0]);
                    mma8(acc[m2][n2 * 2 + 1], a[m2], &b[n2][2]);
                }
        }
        __syncthreads();    // all reads of buffer (c&3) done before it is refilled
    }

#pragma unroll
    for (int m2 = 0; m2 < 4; m2++) {
        const int row = mt * 128 + warpm * 64 + m2 * 16 + gid;
#pragma unroll
        for (int nn = 0; nn < 8; nn++) {
            const int col = nt * 128 + warpn * 64 + nn * 8 + tig * 2;
            const float b0 = bih[col] + bhh[col];
            const float b1 = bih[col + 1] + bhh[col + 1];
            *(float2*)(C + (size_t)row * G4 + col) =
                make_float2(acc[m2][nn][0] + b0, acc[m2][nn][1] + b1);
            *(float2*)(C + (size_t)(row + 8) * G4 + col) =
                make_float2(acc[m2][nn][2] + b0, acc[m2][nn][3] + b1);
        }
    }
}

// ============================================================================
// Persistent LSTM layer (EXACT R11 version, proven 2406us): cluster-2,
// resident Whh slice in smem, h in smem, c in registers, stride 68.
// ============================================================================
#define A_F2S  68                              // A row stride in float2
#define B_F2S  68                              // B row stride in float2
#define A_FLOATS (64 * A_F2S * 2)              // 8704
#define B_FLOATS (256 * B_F2S * 2)             // 34816
#define L_SMEM  ((A_FLOATS + B_FLOATS) * 4)    // 174080 bytes

__global__ __launch_bounds__(512, 1) __cluster_dims__(2, 1, 1)
void lstm_layer(const float* __restrict__ whh_f, const float* __restrict__ whh_b,
                const float* __restrict__ xpf, const float* __restrict__ xpb,
                float* __restrict__ outbuf, int round_out)
{
    extern __shared__ float sl[];
    float*  Afl = sl;
    float2* A2  = (float2*)sl;
    float*  Bfl = sl + A_FLOATS;
    float2* B2  = (float2*)Bfl;

    uint32_t q;
    asm("mov.u32 %0, %%cluster_ctarank;" : "=r"(q));
    const uint32_t peer = q ^ 1u;
    const int rowblk = blockIdx.x >> 1;
    const int dir = blockIdx.y;
    const int row0 = rowblk * 64;
    const float* xp  = dir ? xpb : xpf;
    const float* whh = dir ? whh_b : whh_f;

    const int tid = threadIdx.x, l = tid & 31, w = tid >> 5;
    const int gid = l >> 2, tig = l & 3;
    const int warpm = w >> 3;            // 0..1  (32 rows each)
    const int warpj = w & 7;             // 0..7  (8 j-cols each)

    // ---- load resident Whh slice once: rows n_g = g*128 + q*64 + jl ----
    {
        const int nb = tid >> 1;                 // 0..255 local row
        const int g = nb >> 6, jl = nb & 63;
        const int kh = (tid & 1) * 64;
        const float* src = whh + (size_t)(g * 128 + (int)q * 64 + jl) * HH + kh;
#pragma unroll
        for (int i = 0; i < 16; i++) {
            float4 v = *(const float4*)(src + i * 4);
            const float vv[4] = {tf32r(v.x), tf32r(v.y), tf32r(v.z), tf32r(v.w)};
#pragma unroll
            for (int j = 0; j < 4; j++) {
                const int k = kh + i * 4 + j;
                const int p = (k >> 3) * 4 + (k & 3);
                const int s = (k >> 2) & 1;
                Bfl[nb * (B_F2S * 2) + p * 2 + s] = vv[j];
            }
        }
    }

    // per-thread fixed coordinates
    const int jl2 = warpj * 8 + tig * 2;          // local j of cols (jl2, jl2+1)
    const int jg  = (int)q * 64 + jl2;            // global hidden col
    const int pA  = (jg >> 3) * 4 + (jg & 3);     // A pair index for h writes
    const int sA  = (jg >> 2) & 1;                // slot (same for jg and jg+1)

    float2 cc[4];                                 // cell state (4 rows x 2 cols)

    for (int ti = 0; ti < TT; ti++) {
        const int t = dir ? (TT - 1 - ti) : ti;

        float acc[2][4][4];
#pragma unroll
        for (int m2 = 0; m2 < 2; m2++)
#pragma unroll
            for (int g = 0; g < 4; g++)
#pragma unroll
                for (int r = 0; r < 4; r++) acc[m2][g][r] = 0.0f;

        // prefetch xp for this step (overlaps MMA loop via scoreboard)
        float2 xr[4][4];
#pragma unroll
        for (int r = 0; r < 4; r++) {
            const int brow = row0 + warpm * 32 + (r >> 1) * 16 + (r & 1) * 8 + gid;
            const float* xpr = xp + ((size_t)brow * TT + t) * G4 + jg;
#pragma unroll
            for (int g = 0; g < 4; g++)
                xr[r][g] = *(const float2*)(xpr + g * HH);
        }

        if (ti > 0) {
            const int r0 = warpm * 32 + gid;
#pragma unroll
            for (int kk = 0; kk < 16; kk++) {
                const int p = kk * 4 + tig;
                float2 fa0 = A2[(r0)      * A_F2S + p];
                float2 fa1 = A2[(r0 + 8)  * A_F2S + p];
                float2 fa2 = A2[(r0 + 16) * A_F2S + p];
                float2 fa3 = A2[(r0 + 24) * A_F2S + p];
                const uint32_t a0[4] = {FU(fa0.x), FU(fa1.x), FU(fa0.y), FU(fa1.y)};
                const uint32_t a1[4] = {FU(fa2.x), FU(fa3.x), FU(fa2.y), FU(fa3.y)};
#pragma unroll
                for (int g = 0; g < 4; g++) {
                    const int nb = g * 64 + warpj * 8 + gid;
                    float2 fw = B2[nb * B_F2S + p];
                    const uint32_t bf[2] = {FU(fw.x), FU(fw.y)};
                    mma8(acc[0][g], a0, bf);
                    mma8(acc[1][g], a1, bf);
                }
            }
        }
        __syncthreads();          // all A reads done before cell overwrites A

        // ---- fused LSTM cell; write h to outbuf + both CTAs' A planes ----
#pragma unroll
        for (int r = 0; r < 4; r++) {
            const int m2 = r >> 1, rh = r & 1;
            const int lr = warpm * 32 + m2 * 16 + rh * 8 + gid;
            const int brow = row0 + lr;
            const int e = rh * 2;

            float i0 = sigm(acc[m2][0][e]     + xr[r][0].x);
            float i1 = sigm(acc[m2][0][e + 1] + xr[r][0].y);
            float f0 = sigm(acc[m2][1][e]     + xr[r][1].x);
            float f1 = sigm(acc[m2][1][e + 1] + xr[r][1].y);
            float g0 = tanhf(acc[m2][2][e]     + xr[r][2].x);
            float g1 = tanhf(acc[m2][2][e + 1] + xr[r][2].y);
            float o0 = sigm(acc[m2][3][e]     + xr[r][3].x);
            float o1 = sigm(acc[m2][3][e + 1] + xr[r][3].y);

            float2 cp = (ti > 0) ? cc[r] : make_float2(0.f, 0.f);
            float2 cn = make_float2(f0 * cp.x + i0 * g0, f1 * cp.y + i1 * g1);
            float2 hn = make_float2(o0 * tanhf(cn.x), o1 * tanhf(cn.y));
            cc[r] = cn;

            const float h0 = tf32r(hn.x), h1 = tf32r(hn.y);
            const float2 hw = round_out ? make_float2(h0, h1) : hn;
            *(float2*)(outbuf + ((size_t)brow * TT + t) * 256 + dir * HH + jg) = hw;

            float* dst = &Afl[lr * (A_F2S * 2) + pA * 2 + sA];
            dst[0] = h0;
            dst[2] = h1;                         // pA+1, same slot
            const uint32_t da = smem_u32(dst);
            st_peer(da,     peer, h0);
            st_peer(da + 8, peer, h1);
        }
        __syncthreads();
        asm volatile("barrier.cluster.arrive.aligned;" ::: "memory");
        asm volatile("barrier.cluster.wait.aligned;"   ::: "memory");
    }
}

// ============================================================================
// Max-pool + fc1(relu) + fc2, fused. (unchanged, proven)
// ============================================================================
__global__ void fc_head(const float* __restrict__ out2,
                        const float* __restrict__ w1, const float* __restrict__ b1,
                        const float* __restrict__ w2, const float* __restrict__ b2,
                        float* __restrict__ y)
{
    extern __shared__ float smf[];
    float* wfc = smf;
    float* v   = wfc + 64 * 513;
    float* red = v + 512;
    const int tid = threadIdx.x;

    for (int i = tid; i < 64 * 512; i += 512)
        wfc[(i >> 9) * 513 + (i & 511)] = w1[i];
    __syncthreads();

    const int jj = tid & 63, part = tid >> 6;

    for (int rr = 0; rr < 32; rr++) {
        const int b = blockIdx.x * 32 + rr;
        {
            int c = tid >> 1, p = tid & 1;
            const float* p0 = out2 + ((size_t)b * TT + p * 5) * 256 + c;
            float mx = p0[0];
            mx = fmaxf(mx, p0[256]);  mx = fmaxf(mx, p0[512]);
            mx = fmaxf(mx, p0[768]);  mx = fmaxf(mx, p0[1024]);
            v[tid] = mx;
        }
        __syncthreads();

        float s = 0.0f;
        const float* wr = wfc + jj * 513 + part * 64;
        const float* vr = v + part * 64;
#pragma unroll
        for (int i = 0; i < 64; i++) s += wr[i] * vr[i];
        red[tid] = s;
        __syncthreads();

        if (tid < 64) {
            float h = red[tid]       + red[64 + tid]  + red[128 + tid] +
                      red[192 + tid] + red[256 + tid] + red[320 + tid] +
                      red[384 + tid] + red[448 + tid] + b1[tid];
            h = fmaxf(h, 0.0f);
            red[tid] = h * w2[tid];
        }
        __syncthreads();

        if (tid == 0) {
            float s2 = b2[0];
#pragma unroll
            for (int j2 = 0; j2 < 64; j2++) s2 += red[j2];
            y[b] = s2;
        }
        __syncthreads();
    }
}

// ============================================================================
extern "C" void kernel_launch(void* const* d_in, const int* in_sizes, int n_in,
                              void* d_out, int out_size)
{
    (void)in_sizes; (void)n_in; (void)out_size;
    const float* x     = (const float*)d_in[0];
    const float* wih1f = (const float*)d_in[1];
    const float* whh1f = (const float*)d_in[2];
    const float* bih1f = (const float*)d_in[3];
    const float* bhh1f = (const float*)d_in[4];
    const float* wih1b = (const float*)d_in[5];
    const float* whh1b = (const float*)d_in[6];
    const float* bih1b = (const float*)d_in[7];
    const float* bhh1b = (const float*)d_in[8];
    const float* wih2f = (const float*)d_in[9];
    const float* whh2f = (const float*)d_in[10];
    const float* bih2f = (const float*)d_in[11];
    const float* bhh2f = (const float*)d_in[12];
    const float* wih2b = (const float*)d_in[13];
    const float* whh2b = (const float*)d_in[14];
    const float* bih2b = (const float*)d_in[15];
    const float* bhh2b = (const float*)d_in[16];
    const float* fc1w  = (const float*)d_in[17];
    const float* fc1b  = (const float*)d_in[18];
    const float* fc2w  = (const float*)d_in[19];
    const float* fc2b  = (const float*)d_in[20];
    float* y = (float*)d_out;

    float *xpf, *xpb, *o1, *o2, *xr, *wrb;
    cudaGetSymbolAddress((void**)&xpf, g_xp_f);
    cudaGetSymbolAddress((void**)&xpb, g_xp_b);
    cudaGetSymbolAddress((void**)&o1,  g_out1);
    cudaGetSymbolAddress((void**)&o2,  g_out2);
    cudaGetSymbolAddress((void**)&xr,  g_xr);
    cudaGetSymbolAddress((void**)&wrb, g_wr);
    float* wr1f = wrb + 0 * 512 * 256;
    float* wr1b = wrb + 1 * 512 * 256;
    float* wr2f = wrb + 2 * 512 * 256;
    float* wr2b = wrb + 3 * 512 * 256;

    cudaFuncSetAttribute(xproj_mma, cudaFuncAttributeMaxDynamicSharedMemorySize,
                         (int)XP_SMEM);
    cudaFuncSetAttribute(lstm_layer, cudaFuncAttributeMaxDynamicSharedMemorySize,
                         (int)L_SMEM);

    const dim3 xgrid(4, BT / 128, 2);    // nt, mt, dir(fused f/b)
    const dim3 lgrid(2 * (BN / 64), 2);  // (2 cluster CTAs x 256 blks) x 2 dir

    // ---- pre-round passes ----
    const long long t4x = (long long)BT * (KP1 / 4);
    round_pad<<<(unsigned)((t4x + 255) / 256), 256>>>(x, xr, II, KP1, t4x);
    round_pad<<<(512 * 48 + 255) / 256, 256>>>(wih1f, wr1f, II, KP1, 512 * 48);
    round_pad<<<(512 * 48 + 255) / 256, 256>>>(wih1b, wr1b, II, KP1, 512 * 48);
    round_pad<<<(512 * 64 + 255) / 256, 256>>>(wih2f, wr2f, 256, 256, 512 * 64);
    round_pad<<<(512 * 64 + 255) / 256, 256>>>(wih2b, wr2b, 256, 256, 512 * 64);

    // ---- layer 1 ----
    xproj_mma<<<xgrid, 128, XP_SMEM>>>(xr, wr1f, wr1b, bih1f, bhh1f,
                                       bih1b, bhh1b, xpf, xpb, KP1);
    lstm_layer<<<lgrid, 512, L_SMEM>>>(whh1f, whh1b, xpf, xpb, o1, 1);

    // ---- layer 2 (o1 already tf32-rounded at write) ----
    xproj_mma<<<xgrid, 128, XP_SMEM>>>(o1, wr2f, wr2b, bih2f, bhh2f,
                                       bih2b, bhh2b, xpf, xpb, 256);
    lstm_layer<<<lgrid, 512, L_SMEM>>>(whh2f, whh2b, xpf, xpb, o2, 0);

    // ---- pool + FC head ----
    cudaFuncSetAttribute(fc_head, cudaFuncAttributeMaxDynamicSharedMemorySize,
                         (64 * 513 + 512 + 512) * (int)sizeof(float));
    fc_head<<<BN / 32, 512, (64 * 513 + 512 + 512) * sizeof(float)>>>(
        o2, fc1w, fc1b, fc2w, fc2b, y);
}

// round 14
// speedup vs baseline: 1.5253x; 1.5253x over previous
#include <cuda_runtime.h>
#include <cstdint>
#include <cstddef>

#define BN   16384          // batch
#define TT   10             // timesteps
#define II   184            // input features
#define HH   128            // hidden
#define G4   512            // 4*H (gate width)
#define BT   (BN * TT)      // 163840 rows
#define KP1  192            // padded K for layer-1 xproj

// ---------------- scratch (device globals; allocation-free) ----------------
__device__ float g_xp_f[(size_t)BT * G4];
__device__ float g_xp_b[(size_t)BT * G4];
__device__ float g_out1[(size_t)BT * 256];
__device__ float g_out2[(size_t)BT * 256];
__device__ float g_xr[(size_t)BT * KP1];     // tf32-rounded, padded x
__device__ float g_wr[4][512 * 256];         // rounded, padded w_ih (f,b,f2,b2)

// ---------------- helpers ----------------
__device__ __forceinline__ float sigm(float x) {
    return 1.0f / (1.0f + __expf(-x));
}
__device__ __forceinline__ float tf32r(float x) {
    uint32_t r;
    asm("cvt.rna.tf32.f32 %0, %1;" : "=r"(r) : "f"(x));
    return __uint_as_float(r);
}
__device__ __forceinline__ void mma8(float c[4], const uint32_t a[4],
                                     const uint32_t b[2]) {
    asm volatile(
        "mma.sync.aligned.m16n8k8.row.col.f32.tf32.tf32.f32 "
        "{%0,%1,%2,%3}, {%4,%5,%6,%7}, {%8,%9}, {%0,%1,%2,%3};"
        : "+f"(c[0]), "+f"(c[1]), "+f"(c[2]), "+f"(c[3])
        : "r"(a[0]), "r"(a[1]), "r"(a[2]), "r"(a[3]), "r"(b[0]), "r"(b[1]));
}
#define FU __float_as_uint

__device__ __forceinline__ uint32_t smem_u32(const void* p) {
    uint32_t a;
    asm("{ .reg .u64 t; cvta.to.shared.u64 t, %1; cvt.u32.u64 %0, t; }"
        : "=r"(a) : "l"(p));
    return a;
}
__device__ __forceinline__ void st_peer(uint32_t local_addr, uint32_t peer_rank,
                                        float v) {
    uint32_t pa;
    asm volatile("mapa.shared::cluster.u32 %0, %1, %2;"
                 : "=r"(pa) : "r"(local_addr), "r"(peer_rank));
    asm volatile("st.shared::cluster.f32 [%0], %1;" :: "r"(pa), "f"(v)
                 : "memory");
}

// ============================================================================
// Pre-round pass: dst[row][0..KP) = tf32_rna(src[row][0..K)), zero-padded.
// ============================================================================
__global__ void round_pad(const float* __restrict__ src, float* __restrict__ dst,
                          int K, int KPp, long long total4)
{
    const long long i4 = (long long)blockIdx.x * blockDim.x + threadIdx.x;
    if (i4 >= total4) return;
    const int kp4 = KPp >> 2;
    const long long row = i4 / kp4;
    const int c = (int)(i4 % kp4) * 4;
    float4 v = make_float4(0.f, 0.f, 0.f, 0.f);
    if (c < K) v = *(const float4*)(src + row * K + c);
    float4 o = make_float4(tf32r(v.x), tf32r(v.y), tf32r(v.z), tf32r(v.w));
    *(float4*)(dst + row * KPp + c) = o;
}

// ============================================================================
// xproj GEMM v5: R11 core with a CORRECT 4-stage pipeline.
//   prologue: issue chunks 0,1,2 (3 groups pending)
//   loop top: wait_group 2  -> chunk c complete (c+1, c+2 pending)
//             __syncthreads -> all threads' copies visible
//             issue chunk c+3 into buffer (c+3)&3 == (c-1)&3, whose reads all
//             finished before any thread could pass the top sync
//             compute chunk c; NO trailing barrier needed (4 buffers)
// ============================================================================
#define XST      20480                 // stage bytes: A 128*80 + B 128*80
#define XP_SMEM  (4 * XST)             // 81920

__global__ __launch_bounds__(128, 2)
void xproj_mma(const float* __restrict__ A, const float* __restrict__ W,
               const float* __restrict__ bih, const float* __restrict__ bhh,
               float* __restrict__ C, int KPp)
{
    extern __shared__ char sx[];
    const uint32_t smb = smem_u32(sx);
    const int tid = threadIdx.x, l = tid & 31, w = tid >> 5;
    const int gid = l >> 2, tig = l & 3;
    const int nt = blockIdx.x, mt = blockIdx.y;
    const int warpm = w >> 1, warpn = w & 1;
    const int nblk = KPp >> 4;

    const float* Ag = A + (size_t)mt * 128 * KPp;
    const float* Wg = W + (size_t)nt * 128 * KPp;

    const int ckg = tid & 3, crw = tid >> 2;

    auto issue = [&](int c) {
        const uint32_t sA = smb + (c & 3) * XST;
        const uint32_t sB = sA + 10240;
        const float* ga = Ag + c * 16 + ckg * 4;
        const float* gb = Wg + c * 16 + ckg * 4;
#pragma unroll
        for (int i = 0; i < 4; i++) {
            const int r = crw + i * 32;
            asm volatile("cp.async.cg.shared.global [%0], [%1], 16;"
                         :: "r"(sA + r * 80 + ckg * 16),
                            "l"(ga + (size_t)r * KPp) : "memory");
            asm volatile("cp.async.cg.shared.global [%0], [%1], 16;"
                         :: "r"(sB + r * 80 + ckg * 16),
                            "l"(gb + (size_t)r * KPp) : "memory");
        }
    };

    const int lj = l >> 3, li = l & 7;
    const uint32_t offA = (uint32_t)((warpm * 64 + (lj & 1) * 8 + li) * 80
                                     + (lj >> 1) * 16);
    const uint32_t offB = (uint32_t)(10240 + (warpn * 64 + (lj >> 1) * 8 + li) * 80
                                     + (lj & 1) * 16);

    float acc[4][8][4];
#pragma unroll
    for (int m2 = 0; m2 < 4; m2++)
#pragma unroll
        for (int nn = 0; nn < 8; nn++)
#pragma unroll
            for (int r = 0; r < 4; r++) acc[m2][nn][r] = 0.0f;

    issue(0); asm volatile("cp.async.commit_group;" ::: "memory");
    issue(1); asm volatile("cp.async.commit_group;" ::: "memory");
    issue(2); asm volatile("cp.async.commit_group;" ::: "memory");

    for (int c = 0; c < nblk; c++) {
        asm volatile("cp.async.wait_group 2;" ::: "memory");  // chunk c done
        __syncthreads();                                       // visible to all
        if (c + 3 < nblk) issue(c + 3);
        asm volatile("cp.async.commit_group;" ::: "memory");   // empty ok
        const uint32_t stg = smb + (c & 3) * XST;
#pragma unroll
        for (int kk = 0; kk < 2; kk++) {
            uint32_t a[4][4], b[4][4];
#pragma unroll
            for (int m2 = 0; m2 < 4; m2++)
                asm volatile(
                    "ldmatrix.sync.aligned.m8n8.x4.shared.b16 {%0,%1,%2,%3}, [%4];"
                    : "=r"(a[m2][0]), "=r"(a[m2][1]),
                      "=r"(a[m2][2]), "=r"(a[m2][3])
                    : "r"(stg + offA + m2 * 1280 + kk * 32));
#pragma unroll
            for (int n2 = 0; n2 < 4; n2++)
                asm volatile(
                    "ldmatrix.sync.aligned.m8n8.x4.shared.b16 {%0,%1,%2,%3}, [%4];"
                    : "=r"(b[n2][0]), "=r"(b[n2][1]),
                      "=r"(b[n2][2]), "=r"(b[n2][3])
                    : "r"(stg + offB + n2 * 1280 + kk * 32));
#pragma unroll
            for (int m2 = 0; m2 < 4; m2++)
#pragma unroll
                for (int n2 = 0; n2 < 4; n2++) {
                    mma8(acc[m2][n2 * 2],     a[m2], &b[n2][0]);
                    mma8(acc[m2][n2 * 2 + 1], a[m2], &b[n2][2]);
                }
        }
    }

#pragma unroll
    for (int m2 = 0; m2 < 4; m2++) {
        const int row = mt * 128 + warpm * 64 + m2 * 16 + gid;
#pragma unroll
        for (int nn = 0; nn < 8; nn++) {
            const int col = nt * 128 + warpn * 64 + nn * 8 + tig * 2;
            const float b0 = bih[col] + bhh[col];
            const float b1 = bih[col + 1] + bhh[col + 1];
            *(float2*)(C + (size_t)row * G4 + col) =
                make_float2(acc[m2][nn][0] + b0, acc[m2][nn][1] + b1);
            *(float2*)(C + (size_t)(row + 8) * G4 + col) =
                make_float2(acc[m2][nn][2] + b0, acc[m2][nn][3] + b1);
        }
    }
}

// ============================================================================
// Persistent LSTM layer (EXACT R11 version, proven 2406us): cluster-2,
// resident Whh slice in smem, h in smem, c in registers, stride 68.
// ============================================================================
#define A_F2S  68                              // A row stride in float2
#define B_F2S  68                              // B row stride in float2
#define A_FLOATS (64 * A_F2S * 2)              // 8704
#define B_FLOATS (256 * B_F2S * 2)             // 34816
#define L_SMEM  ((A_FLOATS + B_FLOATS) * 4)    // 174080 bytes

__global__ __launch_bounds__(512, 1) __cluster_dims__(2, 1, 1)
void lstm_layer(const float* __restrict__ whh_f, const float* __restrict__ whh_b,
                const float* __restrict__ xpf, const float* __restrict__ xpb,
                float* __restrict__ outbuf, int round_out)
{
    extern __shared__ float sl[];
    float*  Afl = sl;
    float2* A2  = (float2*)sl;
    float*  Bfl = sl + A_FLOATS;
    float2* B2  = (float2*)Bfl;

    uint32_t q;
    asm("mov.u32 %0, %%cluster_ctarank;" : "=r"(q));
    const uint32_t peer = q ^ 1u;
    const int rowblk = blockIdx.x >> 1;
    const int dir = blockIdx.y;
    const int row0 = rowblk * 64;
    const float* xp  = dir ? xpb : xpf;
    const float* whh = dir ? whh_b : whh_f;

    const int tid = threadIdx.x, l = tid & 31, w = tid >> 5;
    const int gid = l >> 2, tig = l & 3;
    const int warpm = w >> 3;            // 0..1  (32 rows each)
    const int warpj = w & 7;             // 0..7  (8 j-cols each)

    // ---- load resident Whh slice once: rows n_g = g*128 + q*64 + jl ----
    {
        const int nb = tid >> 1;                 // 0..255 local row
        const int g = nb >> 6, jl = nb & 63;
        const int kh = (tid & 1) * 64;
        const float* src = whh + (size_t)(g * 128 + (int)q * 64 + jl) * HH + kh;
#pragma unroll
        for (int i = 0; i < 16; i++) {
            float4 v = *(const float4*)(src + i * 4);
            const float vv[4] = {tf32r(v.x), tf32r(v.y), tf32r(v.z), tf32r(v.w)};
#pragma unroll
            for (int j = 0; j < 4; j++) {
                const int k = kh + i * 4 + j;
                const int p = (k >> 3) * 4 + (k & 3);
                const int s = (k >> 2) & 1;
                Bfl[nb * (B_F2S * 2) + p * 2 + s] = vv[j];
            }
        }
    }

    // per-thread fixed coordinates
    const int jl2 = warpj * 8 + tig * 2;          // local j of cols (jl2, jl2+1)
    const int jg  = (int)q * 64 + jl2;            // global hidden col
    const int pA  = (jg >> 3) * 4 + (jg & 3);     // A pair index for h writes
    const int sA  = (jg >> 2) & 1;                // slot (same for jg and jg+1)

    float2 cc[4];                                 // cell state (4 rows x 2 cols)

    for (int ti = 0; ti < TT; ti++) {
        const int t = dir ? (TT - 1 - ti) : ti;

        float acc[2][4][4];
#pragma unroll
        for (int m2 = 0; m2 < 2; m2++)
#pragma unroll
            for (int g = 0; g < 4; g++)
#pragma unroll
                for (int r = 0; r < 4; r++) acc[m2][g][r] = 0.0f;

        // prefetch xp for this step (overlaps MMA loop via scoreboard)
        float2 xr[4][4];
#pragma unroll
        for (int r = 0; r < 4; r++) {
            const int brow = row0 + warpm * 32 + (r >> 1) * 16 + (r & 1) * 8 + gid;
            const float* xpr = xp + ((size_t)brow * TT + t) * G4 + jg;
#pragma unroll
            for (int g = 0; g < 4; g++)
                xr[r][g] = *(const float2*)(xpr + g * HH);
        }

        if (ti > 0) {
            const int r0 = warpm * 32 + gid;
#pragma unroll
            for (int kk = 0; kk < 16; kk++) {
                const int p = kk * 4 + tig;
                float2 fa0 = A2[(r0)      * A_F2S + p];
                float2 fa1 = A2[(r0 + 8)  * A_F2S + p];
                float2 fa2 = A2[(r0 + 16) * A_F2S + p];
                float2 fa3 = A2[(r0 + 24) * A_F2S + p];
                const uint32_t a0[4] = {FU(fa0.x), FU(fa1.x), FU(fa0.y), FU(fa1.y)};
                const uint32_t a1[4] = {FU(fa2.x), FU(fa3.x), FU(fa2.y), FU(fa3.y)};
#pragma unroll
                for (int g = 0; g < 4; g++) {
                    const int nb = g * 64 + warpj * 8 + gid;
                    float2 fw = B2[nb * B_F2S + p];
                    const uint32_t bf[2] = {FU(fw.x), FU(fw.y)};
                    mma8(acc[0][g], a0, bf);
                    mma8(acc[1][g], a1, bf);
                }
            }
        }
        __syncthreads();          // all A reads done before cell overwrites A

        // ---- fused LSTM cell; write h to outbuf + both CTAs' A planes ----
#pragma unroll
        for (int r = 0; r < 4; r++) {
            const int m2 = r >> 1, rh = r & 1;
            const int lr = warpm * 32 + m2 * 16 + rh * 8 + gid;
            const int brow = row0 + lr;
            const int e = rh * 2;

            float i0 = sigm(acc[m2][0][e]     + xr[r][0].x);
            float i1 = sigm(acc[m2][0][e + 1] + xr[r][0].y);
            float f0 = sigm(acc[m2][1][e]     + xr[r][1].x);
            float f1 = sigm(acc[m2][1][e + 1] + xr[r][1].y);
            float g0 = tanhf(acc[m2][2][e]     + xr[r][2].x);
            float g1 = tanhf(acc[m2][2][e + 1] + xr[r][2].y);
            float o0 = sigm(acc[m2][3][e]     + xr[r][3].x);
            float o1 = sigm(acc[m2][3][e + 1] + xr[r][3].y);

            float2 cp = (ti > 0) ? cc[r] : make_float2(0.f, 0.f);
            float2 cn = make_float2(f0 * cp.x + i0 * g0, f1 * cp.y + i1 * g1);
            float2 hn = make_float2(o0 * tanhf(cn.x), o1 * tanhf(cn.y));
            cc[r] = cn;

            const float h0 = tf32r(hn.x), h1 = tf32r(hn.y);
            const float2 hw = round_out ? make_float2(h0, h1) : hn;
            *(float2*)(outbuf + ((size_t)brow * TT + t) * 256 + dir * HH + jg) = hw;

            float* dst = &Afl[lr * (A_F2S * 2) + pA * 2 + sA];
            dst[0] = h0;
            dst[2] = h1;                         // pA+1, same slot
            const uint32_t da = smem_u32(dst);
            st_peer(da,     peer, h0);
            st_peer(da + 8, peer, h1);
        }
        __syncthreads();
        asm volatile("barrier.cluster.arrive.aligned;" ::: "memory");
        asm volatile("barrier.cluster.wait.aligned;"   ::: "memory");
    }
}

// ============================================================================
// Max-pool + fc1(relu) + fc2, fused. (unchanged, proven)
// ============================================================================
__global__ void fc_head(const float* __restrict__ out2,
                        const float* __restrict__ w1, const float* __restrict__ b1,
                        const float* __restrict__ w2, const float* __restrict__ b2,
                        float* __restrict__ y)
{
    extern __shared__ float smf[];
    float* wfc = smf;
    float* v   = wfc + 64 * 513;
    float* red = v + 512;
    const int tid = threadIdx.x;

    for (int i = tid; i < 64 * 512; i += 512)
        wfc[(i >> 9) * 513 + (i & 511)] = w1[i];
    __syncthreads();

    const int jj = tid & 63, part = tid >> 6;

    for (int rr = 0; rr < 32; rr++) {
        const int b = blockIdx.x * 32 + rr;
        {
            int c = tid >> 1, p = tid & 1;
            const float* p0 = out2 + ((size_t)b * TT + p * 5) * 256 + c;
            float mx = p0[0];
            mx = fmaxf(mx, p0[256]);  mx = fmaxf(mx, p0[512]);
            mx = fmaxf(mx, p0[768]);  mx = fmaxf(mx, p0[1024]);
            v[tid] = mx;
        }
        __syncthreads();

        float s = 0.0f;
        const float* wr = wfc + jj * 513 + part * 64;
        const float* vr = v + part * 64;
#pragma unroll
        for (int i = 0; i < 64; i++) s += wr[i] * vr[i];
        red[tid] = s;
        __syncthreads();

        if (tid < 64) {
            float h = red[tid]       + red[64 + tid]  + red[128 + tid] +
                      red[192 + tid] + red[256 + tid] + red[320 + tid] +
                      red[384 + tid] + red[448 + tid] + b1[tid];
            h = fmaxf(h, 0.0f);
            red[tid] = h * w2[tid];
        }
        __syncthreads();

        if (tid == 0) {
            float s2 = b2[0];
#pragma unroll
            for (int j2 = 0; j2 < 64; j2++) s2 += red[j2];
            y[b] = s2;
        }
        __syncthreads();
    }
}

// ============================================================================
extern "C" void kernel_launch(void* const* d_in, const int* in_sizes, int n_in,
                              void* d_out, int out_size)
{
    (void)in_sizes; (void)n_in; (void)out_size;
    const float* x     = (const float*)d_in[0];
    const float* wih1f = (const float*)d_in[1];
    const float* whh1f = (const float*)d_in[2];
    const float* bih1f = (const float*)d_in[3];
    const float* bhh1f = (const float*)d_in[4];
    const float* wih1b = (const float*)d_in[5];
    const float* whh1b = (const float*)d_in[6];
    const float* bih1b = (const float*)d_in[7];
    const float* bhh1b = (const float*)d_in[8];
    const float* wih2f = (const float*)d_in[9];
    const float* whh2f = (const float*)d_in[10];
    const float* bih2f = (const float*)d_in[11];
    const float* bhh2f = (const float*)d_in[12];
    const float* wih2b = (const float*)d_in[13];
    const float* whh2b = (const float*)d_in[14];
    const float* bih2b = (const float*)d_in[15];
    const float* bhh2b = (const float*)d_in[16];
    const float* fc1w  = (const float*)d_in[17];
    const float* fc1b  = (const float*)d_in[18];
    const float* fc2w  = (const float*)d_in[19];
    const float* fc2b  = (const float*)d_in[20];
    float* y = (float*)d_out;

    float *xpf, *xpb, *o1, *o2, *xr, *wrb;
    cudaGetSymbolAddress((void**)&xpf, g_xp_f);
    cudaGetSymbolAddress((void**)&xpb, g_xp_b);
    cudaGetSymbolAddress((void**)&o1,  g_out1);
    cudaGetSymbolAddress((void**)&o2,  g_out2);
    cudaGetSymbolAddress((void**)&xr,  g_xr);
    cudaGetSymbolAddress((void**)&wrb, g_wr);
    float* wr1f = wrb + 0 * 512 * 256;
    float* wr1b = wrb + 1 * 512 * 256;
    float* wr2f = wrb + 2 * 512 * 256;
    float* wr2b = wrb + 3 * 512 * 256;

    cudaFuncSetAttribute(xproj_mma, cudaFuncAttributeMaxDynamicSharedMemorySize,
                         (int)XP_SMEM);
    cudaFuncSetAttribute(lstm_layer, cudaFuncAttributeMaxDynamicSharedMemorySize,
                         (int)L_SMEM);

    const dim3 xgrid(4, BT / 128);       // nt fastest -> A-tile L2 reuse
    const dim3 lgrid(2 * (BN / 64), 2);  // (2 cluster CTAs x 256 blks) x 2 dir

    // ---- pre-round passes ----
    const long long t4x = (long long)BT * (KP1 / 4);
    round_pad<<<(unsigned)((t4x + 255) / 256), 256>>>(x, xr, II, KP1, t4x);
    round_pad<<<(512 * 48 + 255) / 256, 256>>>(wih1f, wr1f, II, KP1, 512 * 48);
    round_pad<<<(512 * 48 + 255) / 256, 256>>>(wih1b, wr1b, II, KP1, 512 * 48);
    round_pad<<<(512 * 64 + 255) / 256, 256>>>(wih2f, wr2f, 256, 256, 512 * 64);
    round_pad<<<(512 * 64 + 255) / 256, 256>>>(wih2b, wr2b, 256, 256, 512 * 64);

    // ---- layer 1 ----
    xproj_mma<<<xgrid, 128, XP_SMEM>>>(xr, wr1f, bih1f, bhh1f, xpf, KP1);
    xproj_mma<<<xgrid, 128, XP_SMEM>>>(xr, wr1b, bih1b, bhh1b, xpb, KP1);
    lstm_layer<<<lgrid, 512, L_SMEM>>>(whh1f, whh1b, xpf, xpb, o1, 1);

    // ---- layer 2 (o1 already tf32-rounded at write) ----
    xproj_mma<<<xgrid, 128, XP_SMEM>>>(o1, wr2f, bih2f, bhh2f, xpf, 256);
    xproj_mma<<<xgrid, 128, XP_SMEM>>>(o1, wr2b, bih2b, bhh2b, xpb, 256);
    lstm_layer<<<lgrid, 512, L_SMEM>>>(whh2f, whh2b, xpf, xpb, o2, 0);

    // ---- pool + FC head ----
    cudaFuncSetAttribute(fc_head, cudaFuncAttributeMaxDynamicSharedMemorySize,
                         (64 * 513 + 512 + 512) * (int)sizeof(float));
    fc_head<<<BN / 32, 512, (64 * 513 + 512 + 512) * sizeof(float)>>>(
        o2, fc1w, fc1b, fc2w, fc2b, y);
}

// round 15
// speedup vs baseline: 1.6003x; 1.0492x over previous
#include <cuda_runtime.h>
#include <cuda_fp16.h>
#include <cstdint>
#include <cstddef>

#define BN   16384          // batch
#define TT   10             // timesteps
#define II   184            // input features
#define HH   128            // hidden
#define G4   512            // 4*H (gate width)
#define BT   (BN * TT)      // 163840 rows
#define KP1  192            // padded K for layer-1 xproj

// ---------------- scratch (device globals; allocation-free) ----------------
__device__ float g_xp_f[(size_t)BT * G4];
__device__ float g_xp_b[(size_t)BT * G4];
__device__ float g_out1[(size_t)BT * 256];
__device__ float g_out2[(size_t)BT * 256];
__device__ float g_xr[(size_t)BT * KP1];     // tf32-rounded, padded x
__device__ float g_wr[4][512 * 256];         // rounded, padded w_ih (f,b,f2,b2)

// ---------------- helpers ----------------
__device__ __forceinline__ float sigm(float x) {
    return 1.0f / (1.0f + __expf(-x));
}
__device__ __forceinline__ float tf32r(float x) {
    uint32_t r;
    asm("cvt.rna.tf32.f32 %0, %1;" : "=r"(r) : "f"(x));
    return __uint_as_float(r);
}
__device__ __forceinline__ void mma8(float c[4], const uint32_t a[4],
                                     const uint32_t b[2]) {
    asm volatile(
        "mma.sync.aligned.m16n8k8.row.col.f32.tf32.tf32.f32 "
        "{%0,%1,%2,%3}, {%4,%5,%6,%7}, {%8,%9}, {%0,%1,%2,%3};"
        : "+f"(c[0]), "+f"(c[1]), "+f"(c[2]), "+f"(c[3])
        : "r"(a[0]), "r"(a[1]), "r"(a[2]), "r"(a[3]), "r"(b[0]), "r"(b[1]));
}
// fp16 m16n8k16 MMA (2x tf32 rate, same 11-bit mantissa, fp32 accumulate)
__device__ __forceinline__ void mma16(float c[4], const uint32_t a[4],
                                      const uint32_t b[2]) {
    asm volatile(
        "mma.sync.aligned.m16n8k16.row.col.f32.f16.f16.f32 "
        "{%0,%1,%2,%3}, {%4,%5,%6,%7}, {%8,%9}, {%0,%1,%2,%3};"
        : "+f"(c[0]), "+f"(c[1]), "+f"(c[2]), "+f"(c[3])
        : "r"(a[0]), "r"(a[1]), "r"(a[2]), "r"(a[3]), "r"(b[0]), "r"(b[1]));
}
#define FU __float_as_uint

__device__ __forceinline__ uint32_t smem_u32(const void* p) {
    uint32_t a;
    asm("{ .reg .u64 t; cvta.to.shared.u64 t, %1; cvt.u32.u64 %0, t; }"
        : "=r"(a) : "l"(p));
    return a;
}
__device__ __forceinline__ void st_peer_u32(uint32_t local_addr,
                                            uint32_t peer_rank, uint32_t v) {
    uint32_t pa;
    asm volatile("mapa.shared::cluster.u32 %0, %1, %2;"
                 : "=r"(pa) : "r"(local_addr), "r"(peer_rank));
    asm volatile("st.shared::cluster.u32 [%0], %1;" :: "r"(pa), "r"(v)
                 : "memory");
}

// ============================================================================
// Pre-round pass: dst[row][0..KP) = tf32_rna(src[row][0..K)), zero-padded.
// ============================================================================
__global__ void round_pad(const float* __restrict__ src, float* __restrict__ dst,
                          int K, int KPp, long long total4)
{
    const long long i4 = (long long)blockIdx.x * blockDim.x + threadIdx.x;
    if (i4 >= total4) return;
    const int kp4 = KPp >> 2;
    const long long row = i4 / kp4;
    const int c = (int)(i4 % kp4) * 4;
    float4 v = make_float4(0.f, 0.f, 0.f, 0.f);
    if (c < K) v = *(const float4*)(src + row * K + c);
    float4 o = make_float4(tf32r(v.x), tf32r(v.y), tf32r(v.z), tf32r(v.w));
    *(float4*)(dst + row * KPp + c) = o;
}

// ============================================================================
// xproj GEMM v5 (EXACT R14 version, proven): correct 4-stage cp.async
// pipeline + ldmatrix tf32 MMA.
// ============================================================================
#define XST      20480                 // stage bytes: A 128*80 + B 128*80
#define XP_SMEM  (4 * XST)             // 81920

__global__ __launch_bounds__(128, 2)
void xproj_mma(const float* __restrict__ A, const float* __restrict__ W,
               const float* __restrict__ bih, const float* __restrict__ bhh,
               float* __restrict__ C, int KPp)
{
    extern __shared__ char sx[];
    const uint32_t smb = smem_u32(sx);
    const int tid = threadIdx.x, l = tid & 31, w = tid >> 5;
    const int gid = l >> 2, tig = l & 3;
    const int nt = blockIdx.x, mt = blockIdx.y;
    const int warpm = w >> 1, warpn = w & 1;
    const int nblk = KPp >> 4;

    const float* Ag = A + (size_t)mt * 128 * KPp;
    const float* Wg = W + (size_t)nt * 128 * KPp;

    const int ckg = tid & 3, crw = tid >> 2;

    auto issue = [&](int c) {
        const uint32_t sA = smb + (c & 3) * XST;
        const uint32_t sB = sA + 10240;
        const float* ga = Ag + c * 16 + ckg * 4;
        const float* gb = Wg + c * 16 + ckg * 4;
#pragma unroll
        for (int i = 0; i < 4; i++) {
            const int r = crw + i * 32;
            asm volatile("cp.async.cg.shared.global [%0], [%1], 16;"
                         :: "r"(sA + r * 80 + ckg * 16),
                            "l"(ga + (size_t)r * KPp) : "memory");
            asm volatile("cp.async.cg.shared.global [%0], [%1], 16;"
                         :: "r"(sB + r * 80 + ckg * 16),
                            "l"(gb + (size_t)r * KPp) : "memory");
        }
    };

    const int lj = l >> 3, li = l & 7;
    const uint32_t offA = (uint32_t)((warpm * 64 + (lj & 1) * 8 + li) * 80
                                     + (lj >> 1) * 16);
    const uint32_t offB = (uint32_t)(10240 + (warpn * 64 + (lj >> 1) * 8 + li) * 80
                                     + (lj & 1) * 16);

    float acc[4][8][4];
#pragma unroll
    for (int m2 = 0; m2 < 4; m2++)
#pragma unroll
        for (int nn = 0; nn < 8; nn++)
#pragma unroll
            for (int r = 0; r < 4; r++) acc[m2][nn][r] = 0.0f;

    issue(0); asm volatile("cp.async.commit_group;" ::: "memory");
    issue(1); asm volatile("cp.async.commit_group;" ::: "memory");
    issue(2); asm volatile("cp.async.commit_group;" ::: "memory");

    for (int c = 0; c < nblk; c++) {
        asm volatile("cp.async.wait_group 2;" ::: "memory");  // chunk c done
        __syncthreads();                                       // visible to all
        if (c + 3 < nblk) issue(c + 3);
        asm volatile("cp.async.commit_group;" ::: "memory");   // empty ok
        const uint32_t stg = smb + (c & 3) * XST;
#pragma unroll
        for (int kk = 0; kk < 2; kk++) {
            uint32_t a[4][4], b[4][4];
#pragma unroll
            for (int m2 = 0; m2 < 4; m2++)
                asm volatile(
                    "ldmatrix.sync.aligned.m8n8.x4.shared.b16 {%0,%1,%2,%3}, [%4];"
                    : "=r"(a[m2][0]), "=r"(a[m2][1]),
                      "=r"(a[m2][2]), "=r"(a[m2][3])
                    : "r"(stg + offA + m2 * 1280 + kk * 32));
#pragma unroll
            for (int n2 = 0; n2 < 4; n2++)
                asm volatile(
                    "ldmatrix.sync.aligned.m8n8.x4.shared.b16 {%0,%1,%2,%3}, [%4];"
                    : "=r"(b[n2][0]), "=r"(b[n2][1]),
                      "=r"(b[n2][2]), "=r"(b[n2][3])
                    : "r"(stg + offB + n2 * 1280 + kk * 32));
#pragma unroll
            for (int m2 = 0; m2 < 4; m2++)
#pragma unroll
                for (int n2 = 0; n2 < 4; n2++) {
                    mma8(acc[m2][n2 * 2],     a[m2], &b[n2][0]);
                    mma8(acc[m2][n2 * 2 + 1], a[m2], &b[n2][2]);
                }
        }
    }

#pragma unroll
    for (int m2 = 0; m2 < 4; m2++) {
        const int row = mt * 128 + warpm * 64 + m2 * 16 + gid;
#pragma unroll
        for (int nn = 0; nn < 8; nn++) {
            const int col = nt * 128 + warpn * 64 + nn * 8 + tig * 2;
            const float b0 = bih[col] + bhh[col];
            const float b1 = bih[col + 1] + bhh[col + 1];
            *(float2*)(C + (size_t)row * G4 + col) =
                make_float2(acc[m2][nn][0] + b0, acc[m2][nn][1] + b1);
            *(float2*)(C + (size_t)(row + 8) * G4 + col) =
                make_float2(acc[m2][nn][2] + b0, acc[m2][nn][3] + b1);
        }
    }
}

// ============================================================================
// Persistent LSTM layer v4: fp16 m16n8k16 recurrence (2x tensor rate,
// same 11-bit mantissa as tf32). Structure identical to proven R11 version:
// cluster-2 over hidden-column halves, resident Whh (now fp16, 70KB) in smem,
// h-plane (fp16) in smem, c in registers, DSMEM h exchange (one u32 = 2 cols).
// Row stride 68 half2 = 272B: LDS bank = (4*gid + tig) mod 32, conflict-free.
// ============================================================================
#define AH2    68                              // row stride in half2/u32 words
#define A_H2W  (64 * AH2)                      // 4352 words
#define B_H2W  (256 * AH2)                     // 17408 words
#define L_SMEM ((A_H2W + B_H2W) * 4)           // 87040 bytes

__global__ __launch_bounds__(512, 1) __cluster_dims__(2, 1, 1)
void lstm_layer(const float* __restrict__ whh_f, const float* __restrict__ whh_b,
                const float* __restrict__ xpf, const float* __restrict__ xpb,
                float* __restrict__ outbuf, int round_out)
{
    extern __shared__ uint32_t sh[];
    uint32_t* A32 = sh;                // h plane: 64 rows x 64 half2 (+4 pad)
    uint32_t* B32 = sh + A_H2W;        // Whh slice: 256 rows x 64 half2 (+4 pad)

    uint32_t q;
    asm("mov.u32 %0, %%cluster_ctarank;" : "=r"(q));
    const uint32_t peer = q ^ 1u;
    const int rowblk = blockIdx.x >> 1;
    const int dir = blockIdx.y;
    const int row0 = rowblk * 64;
    const float* xp  = dir ? xpb : xpf;
    const float* whh = dir ? whh_b : whh_f;

    const int tid = threadIdx.x, l = tid & 31, w = tid >> 5;
    const int gid = l >> 2, tig = l & 3;
    const int warpm = w >> 3;            // 0..1  (32 rows each)
    const int warpj = w & 7;             // 0..7  (8 j-cols each)

    // ---- fill resident Whh slice (fp16 pairs), once per layer ----
    {
        const int nb = tid >> 1;                 // 0..255 local gate row
        const int g = nb >> 6, jl = nb & 63;
        const int kw = (tid & 1) * 32;           // half2 word offset
        const float* src = whh + (size_t)(g * 128 + (int)q * 64 + jl) * HH
                         + kw * 2;
#pragma unroll
        for (int i = 0; i < 32; i++) {
            __half2 hv = __floats2half2_rn(src[2 * i], src[2 * i + 1]);
            B32[nb * AH2 + kw + i] = *(uint32_t*)&hv;
        }
    }

    // per-thread fixed coordinates
    const int jl2 = warpj * 8 + tig * 2;          // local j of cols (jl2, jl2+1)
    const int jg  = (int)q * 64 + jl2;            // global hidden col (even)
    const int wdA = jg >> 1;                      // half2 word in A row

    float2 cc[4];                                 // cell state (4 rows x 2 cols)

    for (int ti = 0; ti < TT; ti++) {
        const int t = dir ? (TT - 1 - ti) : ti;

        float acc[2][4][4];
#pragma unroll
        for (int m2 = 0; m2 < 2; m2++)
#pragma unroll
            for (int g = 0; g < 4; g++)
#pragma unroll
                for (int r = 0; r < 4; r++) acc[m2][g][r] = 0.0f;

        // prefetch xp for this step (overlaps MMA loop via scoreboard)
        float2 xr[4][4];
#pragma unroll
        for (int r = 0; r < 4; r++) {
            const int brow = row0 + warpm * 32 + (r >> 1) * 16 + (r & 1) * 8 + gid;
            const float* xpr = xp + ((size_t)brow * TT + t) * G4 + jg;
#pragma unroll
            for (int g = 0; g < 4; g++)
                xr[r][g] = *(const float2*)(xpr + g * HH);
        }

        if (ti > 0) {
            const int r0 = warpm * 32 + gid;
#pragma unroll
            for (int c = 0; c < 8; c++) {        // 8 chunks of K=16
                const int wd = c * 8 + tig;
                uint32_t a0[4], a1[4];
                a0[0] = A32[(r0)      * AH2 + wd];
                a0[1] = A32[(r0 + 8)  * AH2 + wd];
                a0[2] = A32[(r0)      * AH2 + wd + 4];
                a0[3] = A32[(r0 + 8)  * AH2 + wd + 4];
                a1[0] = A32[(r0 + 16) * AH2 + wd];
                a1[1] = A32[(r0 + 24) * AH2 + wd];
                a1[2] = A32[(r0 + 16) * AH2 + wd + 4];
                a1[3] = A32[(r0 + 24) * AH2 + wd + 4];
#pragma unroll
                for (int g = 0; g < 4; g++) {
                    const int nb = g * 64 + warpj * 8 + gid;
                    const uint32_t bf[2] = { B32[nb * AH2 + wd],
                                             B32[nb * AH2 + wd + 4] };
                    mma16(acc[0][g], a0, bf);
                    mma16(acc[1][g], a1, bf);
                }
            }
        }
        __syncthreads();          // all A reads done before cell overwrites A

        // ---- fused LSTM cell; publish h to outbuf + both CTAs' A planes ----
#pragma unroll
        for (int r = 0; r < 4; r++) {
            const int m2 = r >> 1, rh = r & 1;
            const int lr = warpm * 32 + m2 * 16 + rh * 8 + gid;
            const int brow = row0 + lr;
            const int e = rh * 2;

            float i0 = sigm(acc[m2][0][e]     + xr[r][0].x);
            float i1 = sigm(acc[m2][0][e + 1] + xr[r][0].y);
            float f0 = sigm(acc[m2][1][e]     + xr[r][1].x);
            float f1 = sigm(acc[m2][1][e + 1] + xr[r][1].y);
            float g0 = tanhf(acc[m2][2][e]     + xr[r][2].x);
            float g1 = tanhf(acc[m2][2][e + 1] + xr[r][2].y);
            float o0 = sigm(acc[m2][3][e]     + xr[r][3].x);
            float o1 = sigm(acc[m2][3][e + 1] + xr[r][3].y);

            float2 cp = (ti > 0) ? cc[r] : make_float2(0.f, 0.f);
            float2 cn = make_float2(f0 * cp.x + i0 * g0, f1 * cp.y + i1 * g1);
            float2 hn = make_float2(o0 * tanhf(cn.x), o1 * tanhf(cn.y));
            cc[r] = cn;

            __half2 hh = __floats2half2_rn(hn.x, hn.y);
            const uint32_t hb = *(uint32_t*)&hh;

            // layer-1: write fp16-rounded h (exact tf32 subset -> feeds xproj)
            const float2 hw = round_out
                ? make_float2(__half2float(__low2half(hh)),
                              __half2float(__high2half(hh)))
                : hn;
            *(float2*)(outbuf + ((size_t)brow * TT + t) * 256 + dir * HH + jg) = hw;

            A32[lr * AH2 + wdA] = hb;                       // own plane
            st_peer_u32(smem_u32(&A32[lr * AH2 + wdA]), peer, hb);
        }
        __syncthreads();
        asm volatile("barrier.cluster.arrive.aligned;" ::: "memory");
        asm volatile("barrier.cluster.wait.aligned;"   ::: "memory");
    }
}

// ============================================================================
// Max-pool + fc1(relu) + fc2, fused. (unchanged, proven)
// ============================================================================
__global__ void fc_head(const float* __restrict__ out2,
                        const float* __restrict__ w1, const float* __restrict__ b1,
                        const float* __restrict__ w2, const float* __restrict__ b2,
                        float* __restrict__ y)
{
    extern __shared__ float smf[];
    float* wfc = smf;
    float* v   = wfc + 64 * 513;
    float* red = v + 512;
    const int tid = threadIdx.x;

    for (int i = tid; i < 64 * 512; i += 512)
        wfc[(i >> 9) * 513 + (i & 511)] = w1[i];
    __syncthreads();

    const int jj = tid & 63, part = tid >> 6;

    for (int rr = 0; rr < 32; rr++) {
        const int b = blockIdx.x * 32 + rr;
        {
            int c = tid >> 1, p = tid & 1;
            const float* p0 = out2 + ((size_t)b * TT + p * 5) * 256 + c;
            float mx = p0[0];
            mx = fmaxf(mx, p0[256]);  mx = fmaxf(mx, p0[512]);
            mx = fmaxf(mx, p0[768]);  mx = fmaxf(mx, p0[1024]);
            v[tid] = mx;
        }
        __syncthreads();

        float s = 0.0f;
        const float* wr = wfc + jj * 513 + part * 64;
        const float* vr = v + part * 64;
#pragma unroll
        for (int i = 0; i < 64; i++) s += wr[i] * vr[i];
        red[tid] = s;
        __syncthreads();

        if (tid < 64) {
            float h = red[tid]       + red[64 + tid]  + red[128 + tid] +
                      red[192 + tid] + red[256 + tid] + red[320 + tid] +
                      red[384 + tid] + red[448 + tid] + b1[tid];
            h = fmaxf(h, 0.0f);
            red[tid] = h * w2[tid];
        }
        __syncthreads();

        if (tid == 0) {
            float s2 = b2[0];
#pragma unroll
            for (int j2 = 0; j2 < 64; j2++) s2 += red[j2];
            y[b] = s2;
        }
        __syncthreads();
    }
}

// ============================================================================
extern "C" void kernel_launch(void* const* d_in, const int* in_sizes, int n_in,
                              void* d_out, int out_size)
{
    (void)in_sizes; (void)n_in; (void)out_size;
    const float* x     = (const float*)d_in[0];
    const float* wih1f = (const float*)d_in[1];
    const float* whh1f = (const float*)d_in[2];
    const float* bih1f = (const float*)d_in[3];
    const float* bhh1f = (const float*)d_in[4];
    const float* wih1b = (const float*)d_in[5];
    const float* whh1b = (const float*)d_in[6];
    const float* bih1b = (const float*)d_in[7];
    const float* bhh1b = (const float*)d_in[8];
    const float* wih2f = (const float*)d_in[9];
    const float* whh2f = (const float*)d_in[10];
    const float* bih2f = (const float*)d_in[11];
    const float* bhh2f = (const float*)d_in[12];
    const float* wih2b = (const float*)d_in[13];
    const float* whh2b = (const float*)d_in[14];
    const float* bih2b = (const float*)d_in[15];
    const float* bhh2b = (const float*)d_in[16];
    const float* fc1w  = (const float*)d_in[17];
    const float* fc1b  = (const float*)d_in[18];
    const float* fc2w  = (const float*)d_in[19];
    const float* fc2b  = (const float*)d_in[20];
    float* y = (float*)d_out;

    float *xpf, *xpb, *o1, *o2, *xr, *wrb;
    cudaGetSymbolAddress((void**)&xpf, g_xp_f);
    cudaGetSymbolAddress((void**)&xpb, g_xp_b);
    cudaGetSymbolAddress((void**)&o1,  g_out1);
    cudaGetSymbolAddress((void**)&o2,  g_out2);
    cudaGetSymbolAddress((void**)&xr,  g_xr);
    cudaGetSymbolAddress((void**)&wrb, g_wr);
    float* wr1f = wrb + 0 * 512 * 256;
    float* wr1b = wrb + 1 * 512 * 256;
    float* wr2f = wrb + 2 * 512 * 256;
    float* wr2b = wrb + 3 * 512 * 256;

    cudaFuncSetAttribute(xproj_mma, cudaFuncAttributeMaxDynamicSharedMemorySize,
                         (int)XP_SMEM);
    cudaFuncSetAttribute(lstm_layer, cudaFuncAttributeMaxDynamicSharedMemorySize,
                         (int)L_SMEM);

    const dim3 xgrid(4, BT / 128);       // nt fastest -> A-tile L2 reuse
    const dim3 lgrid(2 * (BN / 64), 2);  // (2 cluster CTAs x 256 blks) x 2 dir

    // ---- pre-round passes ----
    const long long t4x = (long long)BT * (KP1 / 4);
    round_pad<<<(unsigned)((t4x + 255) / 256), 256>>>(x, xr, II, KP1, t4x);
    round_pad<<<(512 * 48 + 255) / 256, 256>>>(wih1f, wr1f, II, KP1, 512 * 48);
    round_pad<<<(512 * 48 + 255) / 256, 256>>>(wih1b, wr1b, II, KP1, 512 * 48);
    round_pad<<<(512 * 64 + 255) / 256, 256>>>(wih2f, wr2f, 256, 256, 512 * 64);
    round_pad<<<(512 * 64 + 255) / 256, 256>>>(wih2b, wr2b, 256, 256, 512 * 64);

    // ---- layer 1 ----
    xproj_mma<<<xgrid, 128, XP_SMEM>>>(xr, wr1f, bih1f, bhh1f, xpf, KP1);
    xproj_mma<<<xgrid, 128, XP_SMEM>>>(xr, wr1b, bih1b, bhh1b, xpb, KP1);
    lstm_layer<<<lgrid, 512, L_SMEM>>>(whh1f, whh1b, xpf, xpb, o1, 1);

    // ---- layer 2 (o1 fp16-rounded at write -> exact tf32 for xproj) ----
    xproj_mma<<<xgrid, 128, XP_SMEM>>>(o1, wr2f, bih2f, bhh2f, xpf, 256);
    xproj_mma<<<xgrid, 128, XP_SMEM>>>(o1, wr2b, bih2b, bhh2b, xpb, 256);
    lstm_layer<<<lgrid, 512, L_SMEM>>>(whh2f, whh2b, xpf, xpb, o2, 0);

    // ---- pool + FC head ----
    cudaFuncSetAttribute(fc_head, cudaFuncAttributeMaxDynamicSharedMemorySize,
                         (64 * 513 + 512 + 512) * (int)sizeof(float));
    fc_head<<<BN / 32, 512, (64 * 513 + 512 + 512) * sizeof(float)>>>(
        o2, fc1w, fc1b, fc2w, fc2b, y);
}